// round 7
// baseline (speedup 1.0000x reference)
#include <cuda_runtime.h>

#define NB 64
#define NT 512
#define NI 512
#define NH 512
#define NG 2048      // 4*H
#define GRID_R 128   // recurrent persistent CTAs

// ---------------- device scratch (static: no allocs allowed) ----------------
__device__ float g_xg[(long long)NT * NG * NB];      // [t][gate][b]  (256 MB)
__device__ float4 g_hA[2][128 * 32];                 // half A: [k4][b32] quads
__device__ float4 g_hB[2][128 * 32];                 // half B
__device__ unsigned g_cntA[8 * 32];                  // group counters (128B apart)
__device__ unsigned g_cntB[8 * 32];
__device__ unsigned g_rootA[32];                     // root counters (padded)
__device__ unsigned g_rootB[32];

// ---------------- f32x2 packed-FMA helpers (Blackwell FFMA2) ----------------
__device__ __forceinline__ unsigned long long dup2(float x) {
    unsigned long long r;
    asm("mov.b64 %0, {%1,%1};" : "=l"(r) : "f"(x));
    return r;
}
__device__ __forceinline__ void fma2(unsigned long long& d,
                                     unsigned long long a,
                                     unsigned long long b) {
    asm("fma.rn.f32x2 %0, %1, %2, %0;" : "+l"(d) : "l"(a), "l"(b));
}
__device__ __forceinline__ float2 unpack2(unsigned long long v) {
    float lo, hi;
    asm("mov.b64 {%0,%1}, %2;" : "=f"(lo), "=f"(hi) : "l"(v));
    return make_float2(lo, hi);
}

// ---------------- split grid barrier (monotonic tickets, replay-safe) -------
// tid0 only, after __syncthreads. Returns the root target for the matching wait.
__device__ __forceinline__ unsigned bar_arrive(unsigned* grp, unsigned* root) {
    __threadfence();                                   // release this CTA's writes
    unsigned g = (blockIdx.x & 7) << 5;
    unsigned a = atomicAdd(&grp[g], 1u);
    if ((a & 15u) == 15u) atomicAdd(root, 1u);         // 16 CTAs/group, 8 groups
    return ((a >> 4) + 1u) * 8u;
}
__device__ __forceinline__ void bar_wait(unsigned* root, unsigned target) {
    const volatile unsigned* vr = (const volatile unsigned*)root;
    while (*vr < target) {}
    __threadfence();                                   // acquire peers' writes
}

// ---------------- xg GEMM: [32768,512] x [512,2048]^T -> g_xg[t][g][b] -------
#define STS_TILE(bufi)                                                         \
    do {                                                                       \
        As[bufi][ks + 0][r] = ra0.x; As[bufi][ks + 1][r] = ra0.y;              \
        As[bufi][ks + 2][r] = ra0.z; As[bufi][ks + 3][r] = ra0.w;              \
        As[bufi][ks + 4][r] = ra1.x; As[bufi][ks + 5][r] = ra1.y;              \
        As[bufi][ks + 6][r] = ra1.z; As[bufi][ks + 7][r] = ra1.w;              \
        Bs[bufi][ks + 0][r] = rb0.x; Bs[bufi][ks + 1][r] = rb0.y;              \
        Bs[bufi][ks + 2][r] = rb0.z; Bs[bufi][ks + 3][r] = rb0.w;              \
        Bs[bufi][ks + 4][r] = rb1.x; Bs[bufi][ks + 5][r] = rb1.y;              \
        Bs[bufi][ks + 6][r] = rb1.z; Bs[bufi][ks + 7][r] = rb1.w;              \
    } while (0)

__global__ __launch_bounds__(256, 2) void gemm_xg(const float* __restrict__ x,
                                                  const float* __restrict__ Wih,
                                                  const float* __restrict__ bih,
                                                  const float* __restrict__ bhh) {
    __shared__ __align__(16) float As[2][16][132];
    __shared__ __align__(16) float Bs[2][16][132];

    const int tid = threadIdx.x;
    const int n0 = blockIdx.x * 128;
    const int m0 = blockIdx.y * 128;
    const int tm = tid >> 4;
    const int tn = tid & 15;
    const int r  = tid >> 1;
    const int ks = (tid & 1) * 8;

    const float* pa = x   + (long long)(m0 + r) * NI + ks;
    const float* pb = Wih + (long long)(n0 + r) * NI + ks;

    unsigned long long acc[8][4];
#pragma unroll
    for (int i = 0; i < 8; ++i)
#pragma unroll
        for (int j = 0; j < 4; ++j) acc[i][j] = 0ull;

    float4 ra0, ra1, rb0, rb1;
    ra0 = *(const float4*)(pa);
    ra1 = *(const float4*)(pa + 4);
    rb0 = *(const float4*)(pb);
    rb1 = *(const float4*)(pb + 4);
    STS_TILE(0);
    __syncthreads();

#pragma unroll 1
    for (int kt = 0; kt < 32; ++kt) {
        const int buf = kt & 1;
        if (kt < 31) {
            const float* qa = pa + (kt + 1) * 16;
            const float* qb = pb + (kt + 1) * 16;
            ra0 = *(const float4*)(qa);
            ra1 = *(const float4*)(qa + 4);
            rb0 = *(const float4*)(qb);
            rb1 = *(const float4*)(qb + 4);
        }
#pragma unroll
        for (int kk = 0; kk < 16; ++kk) {
            float4 a0 = *(const float4*)&As[buf][kk][tm * 8];
            float4 a1 = *(const float4*)&As[buf][kk][tm * 8 + 4];
            ulonglong2 b01 = *(const ulonglong2*)&Bs[buf][kk][tn * 8];
            ulonglong2 b23 = *(const ulonglong2*)&Bs[buf][kk][tn * 8 + 4];
            float av[8] = {a0.x, a0.y, a0.z, a0.w, a1.x, a1.y, a1.z, a1.w};
            unsigned long long bp[4] = {b01.x, b01.y, b23.x, b23.y};
#pragma unroll
            for (int i = 0; i < 8; ++i) {
                unsigned long long ad = dup2(av[i]);
                fma2(acc[i][0], ad, bp[0]);
                fma2(acc[i][1], ad, bp[1]);
                fma2(acc[i][2], ad, bp[2]);
                fma2(acc[i][3], ad, bp[3]);
            }
        }
        if (kt < 31) {
            const int nb = buf ^ 1;
            STS_TILE(nb);
            __syncthreads();
        }
    }

    float bias_[8];
#pragma unroll
    for (int j = 0; j < 8; ++j) {
        int n = n0 + tn * 8 + j;
        bias_[j] = bih[n] + bhh[n];
    }
#pragma unroll
    for (int i = 0; i < 8; ++i) {
        int m  = m0 + tm * 8 + i;
        int bb = m >> 9;
        int t  = m & (NT - 1);
        float* orow = g_xg + ((long long)t * NG + (n0 + tn * 8)) * NB + bb;
#pragma unroll
        for (int j2 = 0; j2 < 4; ++j2) {
            float2 v = unpack2(acc[i][j2]);
            orow[(2 * j2) * NB]     = v.x + bias_[2 * j2];
            orow[(2 * j2 + 1) * NB] = v.y + bias_[2 * j2 + 1];
        }
    }
}

// ---------------- one batch-half LSTM phase ---------------------------------
// 512 thr: warp w (=c) covers k-slice [w*32, w*32+32) (8 k4), lane = b (32).
// acc: all 16 (gate,j) rows for this (b, k-slice). Partials reduced via smem;
// fin threads (tid<128: fb=tid&31, fj=(tid>>5)) finalize + cell update.
__device__ __forceinline__ void lstm_phase(
    const float4* __restrict__ hsrc, float4* __restrict__ hdst,
    const float* wsm2, float* red, float* hx,
    float& cs, float& x0, float& x1, float& x2, float& x3,
    int t, int boff, float* __restrict__ out, int tail,
    int tid, int b0, int kbase, int j0, int fb, int fj, int fin) {

    const ulonglong2* hb2 = (const ulonglong2*)hsrc;
    const ulonglong2* wq  = (const ulonglong2*)wsm2 + (kbase << 4);

    unsigned long long acc[16];
#pragma unroll
    for (int r2 = 0; r2 < 16; ++r2) acc[r2] = 0ull;

    ulonglong2 ha = hb2[kbase * 32 + b0];
#pragma unroll
    for (int k4 = 0; k4 < 8; ++k4) {
        ulonglong2 hA = ha;
        if (k4 < 7) ha = hb2[(kbase + k4 + 1) * 32 + b0];   // depth-1 prefetch
        const ulonglong2* wr = wq + (k4 << 4);
#pragma unroll
        for (int r2 = 0; r2 < 16; ++r2) {
            ulonglong2 w = wr[r2];                 // broadcast LDS.128
            fma2(acc[r2], hA.x, w.x);
            fma2(acc[r2], hA.y, w.y);
        }
    }

    const int c = tid >> 5;
#pragma unroll
    for (int r2 = 0; r2 < 16; ++r2) {
        float2 u = unpack2(acc[r2]);
        red[(r2 << 9) + (c << 5) + b0] = u.x + u.y;   // [row][c16][b32]
    }
    __syncthreads();

    float hn = 0.f;
    if (fin) {
        float g4[4];
#pragma unroll
        for (int q = 0; q < 4; ++q) {
            const float* rp = &red[((q * 4 + fj) << 9) + fb];
            float s0 = 0.f, s1 = 0.f, s2 = 0.f, s3 = 0.f;
#pragma unroll
            for (int cc = 0; cc < 16; cc += 4) {
                s0 += rp[(cc + 0) << 5];
                s1 += rp[(cc + 1) << 5];
                s2 += rp[(cc + 2) << 5];
                s3 += rp[(cc + 3) << 5];
            }
            g4[q] = (s0 + s1) + (s2 + s3);
        }
        float gi = g4[0] + x0;
        float gf = g4[1] + x1;
        float gg = g4[2] + x2;
        float go = g4[3] + x3;
        float iv = 1.f / (1.f + __expf(-gi));
        float fv = 1.f / (1.f + __expf(-gf));
        float gv = 2.f / (1.f + __expf(-2.f * gg)) - 1.f;
        float ov = 1.f / (1.f + __expf(-go));
        cs = fv * cs + iv * gv;
        hn = ov * (2.f / (1.f + __expf(-2.f * cs)) - 1.f);
        hx[fj * 32 + fb] = hn;
    }
    __syncthreads();

    if (tid < 32) {
        float4 vv = make_float4(hx[tid], hx[32 + tid], hx[64 + tid], hx[96 + tid]);
        hdst[blockIdx.x * 32 + tid] = vv;                                   // h exchange
        *(float4*)&out[((long long)(boff + tid) * NT + t) * NH + j0] = vv;  // output
        if (tail && t == NT - 1)
            *(float4*)&out[(long long)NB * NT * NH + (boff + tid) * NH + j0] = vv;  // h_T
    }

    // prefetch next step's xg (h-independent)
    if (fin) {
        int tn2 = (t + 1 < NT) ? t + 1 : t;
        const float* xgt = g_xg + (long long)tn2 * NG * NB;
        int jf = j0 + fj;
        x0 = xgt[(0 * NH + jf) * NB + boff + fb];
        x1 = xgt[(1 * NH + jf) * NB + boff + fb];
        x2 = xgt[(2 * NH + jf) * NB + boff + fb];
        x3 = xgt[(3 * NH + jf) * NB + boff + fb];
    }
}

// ---------------- persistent recurrent kernel (interleaved halves) ----------
__global__ __launch_bounds__(512, 1) void lstm_steps(const float* __restrict__ Whh,
                                                     const float* __restrict__ h0,
                                                     const float* __restrict__ c0,
                                                     float* __restrict__ out,
                                                     int tail) {
    __shared__ __align__(16) float wsm2[128 * 16 * 4];   // 32 KB W slice
    __shared__ __align__(16) float red[16 * 16 * 32];    // 32 KB [row][c][b32]
    __shared__ float hx[128];

    const int tid   = threadIdx.x;
    const int b0    = tid & 31;
    const int kbase = (tid >> 5) * 8;       // warp's k4 base
    const int fin   = tid < 128;
    const int fb    = tid & 31;
    const int fj    = (tid >> 5) & 3;
    const int j0    = blockIdx.x * 4;
    const int jf    = j0 + fj;

    // Stage W_hh slice: quad (k4*16 + row) = Whh[q*NH + j0+cc][4k4..4k4+3]
    for (int idx = tid; idx < 128 * 16; idx += 512) {
        int k4  = idx >> 4;
        int row = idx & 15;
        int q   = row >> 2;
        int cc  = row & 3;
        *(float4*)&wsm2[idx * 4] =
            *(const float4*)&Whh[(long long)(q * NH + j0 + cc) * NH + k4 * 4];
    }

    // Repack h0: CTA bid owns k4 = bid for both halves
    if (tid < 128) {
        int b = tid >> 2, jj = tid & 3;
        ((float*)&g_hA[0][blockIdx.x * 32])[b * 4 + jj] = h0[b * NH + j0 + jj];
    } else if (tid < 256) {
        int b = (tid - 128) >> 2, jj = tid & 3;
        ((float*)&g_hB[0][blockIdx.x * 32])[b * 4 + jj] = h0[(b + 32) * NH + j0 + jj];
    }

    float csA = 0.f, csB = 0.f;
    float xA0 = 0.f, xA1 = 0.f, xA2 = 0.f, xA3 = 0.f;
    float xB0 = 0.f, xB1 = 0.f, xB2 = 0.f, xB3 = 0.f;
    if (fin) {
        csA = c0[fb * NH + jf];
        csB = c0[(fb + 32) * NH + jf];
        xA0 = g_xg[(0 * NH + jf) * NB + fb];
        xA1 = g_xg[(1 * NH + jf) * NB + fb];
        xA2 = g_xg[(2 * NH + jf) * NB + fb];
        xA3 = g_xg[(3 * NH + jf) * NB + fb];
        xB0 = g_xg[(0 * NH + jf) * NB + 32 + fb];
        xB1 = g_xg[(1 * NH + jf) * NB + 32 + fb];
        xB2 = g_xg[(2 * NH + jf) * NB + 32 + fb];
        xB3 = g_xg[(3 * NH + jf) * NB + 32 + fb];
    }

    // initial full barrier: h0 repack + wsm2 visible everywhere
    __syncthreads();
    if (tid == 0) {
        unsigned tg = bar_arrive(g_cntA, g_rootA);
        bar_wait(g_rootA, tg);
    }
    __syncthreads();

    int rd = 0;
    unsigned tgA = 0, tgB = 0;

    for (int t = 0; t < NT; ++t) {
        // ---- half A ----
        lstm_phase(g_hA[rd], g_hA[rd ^ 1], wsm2, red, hx,
                   csA, xA0, xA1, xA2, xA3, t, 0, out, tail,
                   tid, b0, kbase, j0, fb, fj, fin);
        __syncthreads();
        if (tid == 0) {
            tgA = bar_arrive(g_cntA, g_rootA);
            if (t > 0) bar_wait(g_rootB, tgB);        // hidden behind A compute
        }
        __syncthreads();

        // ---- half B ----
        lstm_phase(g_hB[rd], g_hB[rd ^ 1], wsm2, red, hx,
                   csB, xB0, xB1, xB2, xB3, t, 32, out, tail,
                   tid, b0, kbase, j0, fb, fj, fin);
        __syncthreads();
        if (tid == 0) {
            tgB = bar_arrive(g_cntB, g_rootB);
            bar_wait(g_rootA, tgA);                   // hidden behind B compute
        }
        __syncthreads();

        rd ^= 1;
    }

    if (tail && fin) {
        out[(long long)NB * NT * NH + NB * NH + fb * NH + jf]        = csA;  // c_T
        out[(long long)NB * NT * NH + NB * NH + (fb + 32) * NH + jf] = csB;
    }
}

// ---------------- launch ----------------
extern "C" void kernel_launch(void* const* d_in, const int* in_sizes, int n_in,
                              void* d_out, int out_size) {
    const float* x   = (const float*)d_in[0];
    const float* h0  = (const float*)d_in[1];
    const float* c0  = (const float*)d_in[2];
    const float* Wih = (const float*)d_in[3];
    const float* Whh = (const float*)d_in[4];
    const float* bih = (const float*)d_in[5];
    const float* bhh = (const float*)d_in[6];
    float* out = (float*)d_out;

    gemm_xg<<<dim3(16, 256), 256>>>(x, Wih, bih, bhh);
    int tail = (out_size >= NB * NT * NH + 2 * NB * NH) ? 1 : 0;
    lstm_steps<<<GRID_R, 512>>>(Whh, h0, c0, out, tail);
}

// round 8
// speedup vs baseline: 1.2835x; 1.2835x over previous
#include <cuda_runtime.h>

#define NB 64
#define NT 512
#define NI 512
#define NH 512
#define NG 2048      // 4*H
#define GRID_R 128   // recurrent persistent CTAs

// ---------------- device scratch (static: no allocs allowed) ----------------
__device__ float g_xg[(long long)NT * NG * NB];   // [t][gate][b]  (256 MB)
__device__ float g_hbuf[2][NH * NB];              // [k4][b][4j] packed
__device__ unsigned g_grp[8 * 32];                // group counters, 128B apart
__device__ unsigned g_root[32];                   // root counter (padded line)

// ---------------- f32x2 packed-FMA helpers (Blackwell FFMA2) ----------------
__device__ __forceinline__ unsigned long long dup2(float x) {
    unsigned long long r;
    asm("mov.b64 %0, {%1,%1};" : "=l"(r) : "f"(x));
    return r;
}
__device__ __forceinline__ void fma2(unsigned long long& d,
                                     unsigned long long a,
                                     unsigned long long b) {
    asm("fma.rn.f32x2 %0, %1, %2, %0;" : "+l"(d) : "l"(a), "l"(b));
}
__device__ __forceinline__ float2 unpack2(unsigned long long v) {
    float lo, hi;
    asm("mov.b64 {%0,%1}, %2;" : "=f"(lo), "=f"(hi) : "l"(v));
    return make_float2(lo, hi);
}

// ---------------- two-level grid barrier (acq_rel atomics, replay-safe) -----
// tid0 only. arrive returns the root target for the matching wait.
__device__ __forceinline__ unsigned bar_arrive() {
    unsigned* grp = &g_grp[(blockIdx.x & 7) << 5];
    unsigned a;
    asm volatile("atom.acq_rel.gpu.global.add.u32 %0, [%1], 1;"
                 : "=r"(a) : "l"(grp) : "memory");
    if ((a & 15u) == 15u)                    // last of 16-CTA group
        asm volatile("red.release.gpu.global.add.u32 [%0], 1;"
                     :: "l"(g_root) : "memory");
    return ((a >> 4) + 1u) * 8u;             // 8 groups per epoch
}
__device__ __forceinline__ void bar_wait(unsigned target) {
    unsigned v;
    do {
        asm volatile("ld.acquire.gpu.global.u32 %0, [%1];"
                     : "=r"(v) : "l"(g_root) : "memory");
    } while ((int)(v - target) < 0);
}

// ---------------- xg GEMM: [32768,512] x [512,2048]^T -> g_xg[t][g][b] -------
#define STS_TILE(bufi)                                                         \
    do {                                                                       \
        As[bufi][ks + 0][r] = ra0.x; As[bufi][ks + 1][r] = ra0.y;              \
        As[bufi][ks + 2][r] = ra0.z; As[bufi][ks + 3][r] = ra0.w;              \
        As[bufi][ks + 4][r] = ra1.x; As[bufi][ks + 5][r] = ra1.y;              \
        As[bufi][ks + 6][r] = ra1.z; As[bufi][ks + 7][r] = ra1.w;              \
        Bs[bufi][ks + 0][r] = rb0.x; Bs[bufi][ks + 1][r] = rb0.y;              \
        Bs[bufi][ks + 2][r] = rb0.z; Bs[bufi][ks + 3][r] = rb0.w;              \
        Bs[bufi][ks + 4][r] = rb1.x; Bs[bufi][ks + 5][r] = rb1.y;              \
        Bs[bufi][ks + 6][r] = rb1.z; Bs[bufi][ks + 7][r] = rb1.w;              \
    } while (0)

__global__ __launch_bounds__(256, 2) void gemm_xg(const float* __restrict__ x,
                                                  const float* __restrict__ Wih,
                                                  const float* __restrict__ bih,
                                                  const float* __restrict__ bhh) {
    __shared__ __align__(16) float As[2][16][132];
    __shared__ __align__(16) float Bs[2][16][132];

    const int tid = threadIdx.x;
    const int n0 = blockIdx.x * 128;
    const int m0 = blockIdx.y * 128;
    const int tm = tid >> 4;
    const int tn = tid & 15;
    const int r  = tid >> 1;
    const int ks = (tid & 1) * 8;

    const float* pa = x   + (long long)(m0 + r) * NI + ks;
    const float* pb = Wih + (long long)(n0 + r) * NI + ks;

    unsigned long long acc[8][4];
#pragma unroll
    for (int i = 0; i < 8; ++i)
#pragma unroll
        for (int j = 0; j < 4; ++j) acc[i][j] = 0ull;

    float4 ra0, ra1, rb0, rb1;
    ra0 = *(const float4*)(pa);
    ra1 = *(const float4*)(pa + 4);
    rb0 = *(const float4*)(pb);
    rb1 = *(const float4*)(pb + 4);
    STS_TILE(0);
    __syncthreads();

#pragma unroll 1
    for (int kt = 0; kt < 32; ++kt) {
        const int buf = kt & 1;
        if (kt < 31) {
            const float* qa = pa + (kt + 1) * 16;
            const float* qb = pb + (kt + 1) * 16;
            ra0 = *(const float4*)(qa);
            ra1 = *(const float4*)(qa + 4);
            rb0 = *(const float4*)(qb);
            rb1 = *(const float4*)(qb + 4);
        }
#pragma unroll
        for (int kk = 0; kk < 16; ++kk) {
            float4 a0 = *(const float4*)&As[buf][kk][tm * 8];
            float4 a1 = *(const float4*)&As[buf][kk][tm * 8 + 4];
            ulonglong2 b01 = *(const ulonglong2*)&Bs[buf][kk][tn * 8];
            ulonglong2 b23 = *(const ulonglong2*)&Bs[buf][kk][tn * 8 + 4];
            float av[8] = {a0.x, a0.y, a0.z, a0.w, a1.x, a1.y, a1.z, a1.w};
            unsigned long long bp[4] = {b01.x, b01.y, b23.x, b23.y};
#pragma unroll
            for (int i = 0; i < 8; ++i) {
                unsigned long long ad = dup2(av[i]);
                fma2(acc[i][0], ad, bp[0]);
                fma2(acc[i][1], ad, bp[1]);
                fma2(acc[i][2], ad, bp[2]);
                fma2(acc[i][3], ad, bp[3]);
            }
        }
        if (kt < 31) {
            const int nb = buf ^ 1;
            STS_TILE(nb);
            __syncthreads();
        }
    }

    float bias_[8];
#pragma unroll
    for (int j = 0; j < 8; ++j) {
        int n = n0 + tn * 8 + j;
        bias_[j] = bih[n] + bhh[n];
    }
#pragma unroll
    for (int i = 0; i < 8; ++i) {
        int m  = m0 + tm * 8 + i;
        int bb = m >> 9;
        int t  = m & (NT - 1);
        float* orow = g_xg + ((long long)t * NG + (n0 + tn * 8)) * NB + bb;
#pragma unroll
        for (int j2 = 0; j2 < 4; ++j2) {
            float2 v = unpack2(acc[i][j2]);
            orow[(2 * j2) * NB]     = v.x + bias_[2 * j2];
            orow[(2 * j2 + 1) * NB] = v.y + bias_[2 * j2 + 1];
        }
    }
}

// ---------------- persistent recurrent kernel ------------------------------
// CTA owns H-columns [4*bid, 4*bid+4). 512 thr = 16 warps; warp w = k-slice
// [w*32, w*32+32). Lane covers 2 batch elems (b0, b0+32), all 16 (gate,j)
// rows: one W LDS.128 feeds 4 FFMA2. 16 k-partials reduced via smem in two
// row-halves; fin threads (tid<256: fb=tid&63, fj=tid>>6) finalize + store.
__global__ __launch_bounds__(512, 1) void lstm_steps(const float* __restrict__ Whh,
                                                     const float* __restrict__ h0,
                                                     const float* __restrict__ c0,
                                                     float* __restrict__ out,
                                                     int tail) {
    __shared__ __align__(16) float wsm2[128 * 16 * 4];   // 32 KB W slice
    __shared__ __align__(16) float red2[8 * 16 * 64];    // 32 KB [rowHalf][c][b]

    const int tid   = threadIdx.x;
    const int b0    = tid & 31;
    const int kbase = (tid >> 5) * 8;       // warp's first k4
    const int fin   = tid < 256;
    const int fb    = tid & 63;
    const int fj    = (tid >> 6) & 3;
    const int j0    = blockIdx.x * 4;
    const int jf    = j0 + fj;

    // Stage W_hh slice: quad (k4*16 + row) = Whh[q*NH + j0+cc][4k4..4k4+3]
    for (int idx = tid; idx < 128 * 16; idx += 512) {
        int k4  = idx >> 4;
        int row = idx & 15;
        int q   = row >> 2;
        int cc  = row & 3;
        *(float4*)&wsm2[idx * 4] =
            *(const float4*)&Whh[(long long)(q * NH + j0 + cc) * NH + k4 * 4];
    }

    // Repack h0 slice: CTA bid owns k4 = bid (256 floats: [b][4j])
    if (tid < 256)
        g_hbuf[0][blockIdx.x * 256 + tid] = h0[(tid >> 2) * NH + j0 + (tid & 3)];

    float cs = 0.f, x0 = 0.f, x1 = 0.f, x2 = 0.f, x3 = 0.f;
    if (fin) {
        cs = c0[fb * NH + jf];
        x0 = g_xg[(0 * NH + jf) * NB + fb];
        x1 = g_xg[(1 * NH + jf) * NB + fb];
        x2 = g_xg[(2 * NH + jf) * NB + fb];
        x3 = g_xg[(3 * NH + jf) * NB + fb];
    }
    int rd = 0;

    // initial full barrier: h0 repack + wsm2 staging visible everywhere
    __syncthreads();
    if (tid == 0) bar_wait(bar_arrive());
    __syncthreads();

    const ulonglong2* wq = (const ulonglong2*)wsm2 + (kbase << 4);

    for (int t = 0; t < NT; ++t) {
        const ulonglong2* hb2 = (const ulonglong2*)g_hbuf[rd];

        unsigned long long acc[16][2];
#pragma unroll
        for (int r2 = 0; r2 < 16; ++r2) { acc[r2][0] = 0ull; acc[r2][1] = 0ull; }

        // depth-4 h prefetch ring (MLP 8 up front)
        ulonglong2 hra[4], hrc[4];
#pragma unroll
        for (int i = 0; i < 4; ++i) {
            hra[i] = hb2[(kbase + i) * 64 + b0];
            hrc[i] = hb2[(kbase + i) * 64 + b0 + 32];
        }
#pragma unroll
        for (int k4 = 0; k4 < 8; ++k4) {
            ulonglong2 hA = hra[k4 & 3], hB = hrc[k4 & 3];
            if (k4 < 4) {
                hra[k4] = hb2[(kbase + k4 + 4) * 64 + b0];
                hrc[k4] = hb2[(kbase + k4 + 4) * 64 + b0 + 32];
            }
            const ulonglong2* wr = wq + (k4 << 4);
#pragma unroll
            for (int r2 = 0; r2 < 16; ++r2) {
                ulonglong2 w = wr[r2];                 // broadcast LDS.128
                fma2(acc[r2][0], hA.x, w.x);
                fma2(acc[r2][0], hA.y, w.y);
                fma2(acc[r2][1], hB.x, w.x);
                fma2(acc[r2][1], hB.y, w.y);
            }
        }

        // next step's xg prefetch (h-independent) — hide DRAM behind reduction
        float nx0 = x0, nx1 = x1, nx2 = x2, nx3 = x3;
        if (fin) {
            int tn2 = (t + 1 < NT) ? t + 1 : t;
            const float* xgt = g_xg + (long long)tn2 * NG * NB;
            nx0 = xgt[(0 * NH + jf) * NB + fb];
            nx1 = xgt[(1 * NH + jf) * NB + fb];
            nx2 = xgt[(2 * NH + jf) * NB + fb];
            nx3 = xgt[(3 * NH + jf) * NB + fb];
        }

        const int c = tid >> 5;
        // ---- half 1: rows 0..7 (gates i, f) ----
#pragma unroll
        for (int r2 = 0; r2 < 8; ++r2) {
            float2 u0 = unpack2(acc[r2][0]);
            float2 u1 = unpack2(acc[r2][1]);
            red2[(r2 << 10) + (c << 6) + b0]      = u0.x + u0.y;
            red2[(r2 << 10) + (c << 6) + b0 + 32] = u1.x + u1.y;
        }
        __syncthreads();
        float gi = x0, gf = x1;
        if (fin) {
            const float* p0 = &red2[((0 * 4 + fj) << 10) + fb];
            const float* p1 = &red2[((1 * 4 + fj) << 10) + fb];
            float a0 = 0.f, a1 = 0.f, a2 = 0.f, a3 = 0.f;
            float d0 = 0.f, d1 = 0.f, d2 = 0.f, d3 = 0.f;
#pragma unroll
            for (int cc = 0; cc < 16; cc += 4) {
                a0 += p0[(cc + 0) << 6]; a1 += p0[(cc + 1) << 6];
                a2 += p0[(cc + 2) << 6]; a3 += p0[(cc + 3) << 6];
                d0 += p1[(cc + 0) << 6]; d1 += p1[(cc + 1) << 6];
                d2 += p1[(cc + 2) << 6]; d3 += p1[(cc + 3) << 6];
            }
            gi += (a0 + a1) + (a2 + a3);
            gf += (d0 + d1) + (d2 + d3);
        }
        __syncthreads();
        // ---- half 2: rows 8..15 (gates g, o) ----
#pragma unroll
        for (int r2 = 8; r2 < 16; ++r2) {
            float2 u0 = unpack2(acc[r2][0]);
            float2 u1 = unpack2(acc[r2][1]);
            red2[((r2 - 8) << 10) + (c << 6) + b0]      = u0.x + u0.y;
            red2[((r2 - 8) << 10) + (c << 6) + b0 + 32] = u1.x + u1.y;
        }
        __syncthreads();
        if (fin) {
            float gg = x2, go = x3;
            const float* p2 = &red2[((0 * 4 + fj) << 10) + fb];
            const float* p3 = &red2[((1 * 4 + fj) << 10) + fb];
            float a0 = 0.f, a1 = 0.f, a2 = 0.f, a3 = 0.f;
            float d0 = 0.f, d1 = 0.f, d2 = 0.f, d3 = 0.f;
#pragma unroll
            for (int cc = 0; cc < 16; cc += 4) {
                a0 += p2[(cc + 0) << 6]; a1 += p2[(cc + 1) << 6];
                a2 += p2[(cc + 2) << 6]; a3 += p2[(cc + 3) << 6];
                d0 += p3[(cc + 0) << 6]; d1 += p3[(cc + 1) << 6];
                d2 += p3[(cc + 2) << 6]; d3 += p3[(cc + 3) << 6];
            }
            gg += (a0 + a1) + (a2 + a3);
            go += (d0 + d1) + (d2 + d3);

            float iv = 1.f / (1.f + __expf(-gi));
            float fv = 1.f / (1.f + __expf(-gf));
            float gv = 2.f / (1.f + __expf(-2.f * gg)) - 1.f;
            float ov = 1.f / (1.f + __expf(-go));
            cs = fv * cs + iv * gv;
            float hn = ov * (2.f / (1.f + __expf(-2.f * cs)) - 1.f);

            // direct scalar stores: h exchange + output (+ h_T)
            g_hbuf[rd ^ 1][blockIdx.x * 256 + fb * 4 + fj] = hn;
            out[((long long)fb * NT + t) * NH + jf] = hn;
            if (tail && t == NT - 1)
                out[(long long)NB * NT * NH + fb * NH + jf] = hn;
        }
        x0 = nx0; x1 = nx1; x2 = nx2; x3 = nx3;

        // grid barrier
        __syncthreads();
        if (tid == 0) bar_wait(bar_arrive());
        __syncthreads();
        rd ^= 1;
    }

    if (tail && fin)
        out[(long long)NB * NT * NH + NB * NH + fb * NH + jf] = cs;   // c_T
}

// ---------------- launch ----------------
extern "C" void kernel_launch(void* const* d_in, const int* in_sizes, int n_in,
                              void* d_out, int out_size) {
    const float* x   = (const float*)d_in[0];
    const float* h0  = (const float*)d_in[1];
    const float* c0  = (const float*)d_in[2];
    const float* Wih = (const float*)d_in[3];
    const float* Whh = (const float*)d_in[4];
    const float* bih = (const float*)d_in[5];
    const float* bhh = (const float*)d_in[6];
    float* out = (float*)d_out;

    gemm_xg<<<dim3(16, 256), 256>>>(x, Wih, bih, bhh);
    int tail = (out_size >= NB * NT * NH + 2 * NB * NH) ? 1 : 0;
    lstm_steps<<<GRID_R, 512>>>(Whh, h0, c0, out, tail);
}

// round 10
// speedup vs baseline: 1.4892x; 1.1602x over previous
#include <cuda_runtime.h>

#define NB 64
#define NT 512
#define NI 512
#define NH 512
#define NG 2048      // 4*H
#define GRID_R 128   // recurrent persistent CTAs

// ---------------- device scratch (static: no allocs allowed) ----------------
__device__ float g_xg[(long long)NT * NB * NG];   // [t][b][g]  (256 MB)
__device__ float g_hbuf[2][NH * NB];              // [k4][b][4j] packed
__device__ unsigned g_grp[8 * 32];                // group counters, 128B apart
__device__ unsigned g_root[32];                   // root counter (padded line)

// ---------------- f32x2 packed-FMA helpers (Blackwell FFMA2) ----------------
__device__ __forceinline__ unsigned long long dup2(float x) {
    unsigned long long r;
    asm("mov.b64 %0, {%1,%1};" : "=l"(r) : "f"(x));
    return r;
}
__device__ __forceinline__ void fma2(unsigned long long& d,
                                     unsigned long long a,
                                     unsigned long long b) {
    asm("fma.rn.f32x2 %0, %1, %2, %0;" : "+l"(d) : "l"(a), "l"(b));
}
__device__ __forceinline__ float2 unpack2(unsigned long long v) {
    float lo, hi;
    asm("mov.b64 {%0,%1}, %2;" : "=f"(lo), "=f"(hi) : "l"(v));
    return make_float2(lo, hi);
}

// ---------------- two-level grid barrier (acq_rel atomics, replay-safe) -----
__device__ __forceinline__ unsigned bar_arrive() {
    unsigned* grp = &g_grp[(blockIdx.x & 7) << 5];
    unsigned a;
    asm volatile("atom.acq_rel.gpu.global.add.u32 %0, [%1], 1;"
                 : "=r"(a) : "l"(grp) : "memory");
    if ((a & 15u) == 15u)                    // last of 16-CTA group
        asm volatile("red.release.gpu.global.add.u32 [%0], 1;"
                     :: "l"(g_root) : "memory");
    return ((a >> 4) + 1u) * 8u;             // 8 groups per epoch
}
__device__ __forceinline__ void bar_wait(unsigned target) {
    unsigned v;
    do {
        asm volatile("ld.acquire.gpu.global.u32 %0, [%1];"
                     : "=r"(v) : "l"(g_root) : "memory");
    } while ((int)(v - target) < 0);
}

// ---------------- xg GEMM: [32768,512] x [512,2048]^T -> g_xg[t][b][g] -------
#define STS_TILE(bufi)                                                         \
    do {                                                                       \
        As[bufi][ks + 0][r] = ra0.x; As[bufi][ks + 1][r] = ra0.y;              \
        As[bufi][ks + 2][r] = ra0.z; As[bufi][ks + 3][r] = ra0.w;              \
        As[bufi][ks + 4][r] = ra1.x; As[bufi][ks + 5][r] = ra1.y;              \
        As[bufi][ks + 6][r] = ra1.z; As[bufi][ks + 7][r] = ra1.w;              \
        Bs[bufi][ks + 0][r] = rb0.x; Bs[bufi][ks + 1][r] = rb0.y;              \
        Bs[bufi][ks + 2][r] = rb0.z; Bs[bufi][ks + 3][r] = rb0.w;              \
        Bs[bufi][ks + 4][r] = rb1.x; Bs[bufi][ks + 5][r] = rb1.y;              \
        Bs[bufi][ks + 6][r] = rb1.z; Bs[bufi][ks + 7][r] = rb1.w;              \
    } while (0)

__global__ __launch_bounds__(256, 2) void gemm_xg(const float* __restrict__ x,
                                                  const float* __restrict__ Wih,
                                                  const float* __restrict__ bih,
                                                  const float* __restrict__ bhh) {
    __shared__ __align__(16) float As[2][16][132];
    __shared__ __align__(16) float Bs[2][16][132];

    const int tid = threadIdx.x;
    const int n0 = blockIdx.x * 128;
    const int m0 = blockIdx.y * 128;
    const int tm = tid >> 4;
    const int tn = tid & 15;
    const int r  = tid >> 1;
    const int ks = (tid & 1) * 8;

    const float* pa = x   + (long long)(m0 + r) * NI + ks;
    const float* pb = Wih + (long long)(n0 + r) * NI + ks;

    unsigned long long acc[8][4];
#pragma unroll
    for (int i = 0; i < 8; ++i)
#pragma unroll
        for (int j = 0; j < 4; ++j) acc[i][j] = 0ull;

    float4 ra0, ra1, rb0, rb1;
    ra0 = *(const float4*)(pa);
    ra1 = *(const float4*)(pa + 4);
    rb0 = *(const float4*)(pb);
    rb1 = *(const float4*)(pb + 4);
    STS_TILE(0);
    __syncthreads();

#pragma unroll 1
    for (int kt = 0; kt < 32; ++kt) {
        const int buf = kt & 1;
        if (kt < 31) {
            const float* qa = pa + (kt + 1) * 16;
            const float* qb = pb + (kt + 1) * 16;
            ra0 = *(const float4*)(qa);
            ra1 = *(const float4*)(qa + 4);
            rb0 = *(const float4*)(qb);
            rb1 = *(const float4*)(qb + 4);
        }
#pragma unroll
        for (int kk = 0; kk < 16; ++kk) {
            float4 a0 = *(const float4*)&As[buf][kk][tm * 8];
            float4 a1 = *(const float4*)&As[buf][kk][tm * 8 + 4];
            ulonglong2 b01 = *(const ulonglong2*)&Bs[buf][kk][tn * 8];
            ulonglong2 b23 = *(const ulonglong2*)&Bs[buf][kk][tn * 8 + 4];
            float av[8] = {a0.x, a0.y, a0.z, a0.w, a1.x, a1.y, a1.z, a1.w};
            unsigned long long bp[4] = {b01.x, b01.y, b23.x, b23.y};
#pragma unroll
            for (int i = 0; i < 8; ++i) {
                unsigned long long ad = dup2(av[i]);
                fma2(acc[i][0], ad, bp[0]);
                fma2(acc[i][1], ad, bp[1]);
                fma2(acc[i][2], ad, bp[2]);
                fma2(acc[i][3], ad, bp[3]);
            }
        }
        if (kt < 31) {
            const int nb = buf ^ 1;
            STS_TILE(nb);
            __syncthreads();
        }
    }

    // Epilogue: +bias, write g_xg[t][b][g] — 8 gate-cols contiguous: coalesced
    float bias_[8];
#pragma unroll
    for (int j = 0; j < 8; ++j) {
        int n = n0 + tn * 8 + j;
        bias_[j] = bih[n] + bhh[n];
    }
#pragma unroll
    for (int i = 0; i < 8; ++i) {
        int m  = m0 + tm * 8 + i;
        int bb = m >> 9;           // batch
        int t  = m & (NT - 1);     // timestep
        float* orow = g_xg + ((long long)t * NB + bb) * NG + n0 + tn * 8;
        float2 v0 = unpack2(acc[i][0]);
        float2 v1 = unpack2(acc[i][1]);
        float2 v2 = unpack2(acc[i][2]);
        float2 v3 = unpack2(acc[i][3]);
        float4 o0 = make_float4(v0.x + bias_[0], v0.y + bias_[1],
                                v1.x + bias_[2], v1.y + bias_[3]);
        float4 o1 = make_float4(v2.x + bias_[4], v2.y + bias_[5],
                                v3.x + bias_[6], v3.y + bias_[7]);
        *(float4*)orow       = o0;
        *(float4*)(orow + 4) = o1;
    }
}

// ---------------- persistent recurrent kernel ------------------------------
// CTA owns H-columns [4*bid, 4*bid+4). 512 thr = 16 warps; warp w = k-slice
// [w*32, w*32+32). Lane covers 2 batch elems (b0, b0+32), all 16 (gate,j)
// rows: one W LDS.128 feeds 4 FFMA2. 16 k-partials reduced via smem in two
// row-halves; fin threads (tid<256: fb=tid&63, fj=tid>>6) finalize the cell.
__global__ __launch_bounds__(512, 1) void lstm_steps(const float* __restrict__ Whh,
                                                     const float* __restrict__ h0,
                                                     const float* __restrict__ c0,
                                                     float* __restrict__ out,
                                                     int tail) {
    __shared__ __align__(16) float wsm2[128 * 16 * 4];   // 32 KB W slice
    __shared__ __align__(16) float red2[8 * 16 * 64];    // 32 KB [rowHalf][c][b]
    __shared__ float hx[256];

    const int tid   = threadIdx.x;
    const int b0    = tid & 31;
    const int kbase = (tid >> 5) * 8;       // warp's first k4
    const int fin   = tid < 256;
    const int fb    = tid & 63;
    const int fj    = (tid >> 6) & 3;
    const int j0    = blockIdx.x * 4;
    const int jf    = j0 + fj;

    // Stage W_hh slice: quad (k4*16 + row) = Whh[q*NH + j0+cc][4k4..4k4+3]
    for (int idx = tid; idx < 128 * 16; idx += 512) {
        int k4  = idx >> 4;
        int row = idx & 15;
        int q   = row >> 2;
        int cc  = row & 3;
        *(float4*)&wsm2[idx * 4] =
            *(const float4*)&Whh[(long long)(q * NH + j0 + cc) * NH + k4 * 4];
    }

    // Repack h0 slice: CTA bid owns k4 = bid (256 floats: [b][4j])
    if (tid < 256)
        g_hbuf[0][blockIdx.x * 256 + tid] = h0[(tid >> 2) * NH + j0 + (tid & 3)];

    float cs = 0.f, x0 = 0.f, x1 = 0.f, x2 = 0.f, x3 = 0.f;
    if (fin) {
        cs = c0[fb * NH + jf];
        const float* xg0 = g_xg + (long long)fb * NG;    // t = 0
        x0 = xg0[0 * NH + jf];
        x1 = xg0[1 * NH + jf];
        x2 = xg0[2 * NH + jf];
        x3 = xg0[3 * NH + jf];
    }
    int rd = 0;

    // initial full barrier: h0 repack + wsm2 staging visible everywhere
    __syncthreads();
    if (tid == 0) bar_wait(bar_arrive());
    __syncthreads();

    const ulonglong2* wq = (const ulonglong2*)wsm2 + (kbase << 4);

    for (int t = 0; t < NT; ++t) {
        const ulonglong2* hb2 = (const ulonglong2*)g_hbuf[rd];

        unsigned long long acc[16][2];
#pragma unroll
        for (int r2 = 0; r2 < 16; ++r2) { acc[r2][0] = 0ull; acc[r2][1] = 0ull; }

        // depth-4 h prefetch ring (MLP 8 up front)
        ulonglong2 hra[4], hrc[4];
#pragma unroll
        for (int i = 0; i < 4; ++i) {
            hra[i] = hb2[(kbase + i) * 64 + b0];
            hrc[i] = hb2[(kbase + i) * 64 + b0 + 32];
        }
#pragma unroll
        for (int k4 = 0; k4 < 8; ++k4) {
            ulonglong2 hA = hra[k4 & 3], hB = hrc[k4 & 3];
            if (k4 < 4) {
                hra[k4] = hb2[(kbase + k4 + 4) * 64 + b0];
                hrc[k4] = hb2[(kbase + k4 + 4) * 64 + b0 + 32];
            }
            const ulonglong2* wr = wq + (k4 << 4);
#pragma unroll
            for (int r2 = 0; r2 < 16; ++r2) {
                ulonglong2 w = wr[r2];                 // broadcast LDS.128
                fma2(acc[r2][0], hA.x, w.x);
                fma2(acc[r2][0], hA.y, w.y);
                fma2(acc[r2][1], hB.x, w.x);
                fma2(acc[r2][1], hB.y, w.y);
            }
        }

        // next step's xg prefetch (h-independent) — hidden behind reduction
        float nx0 = x0, nx1 = x1, nx2 = x2, nx3 = x3;
        if (fin) {
            int tn2 = (t + 1 < NT) ? t + 1 : t;
            const float* xgt = g_xg + ((long long)tn2 * NB + fb) * NG;
            nx0 = xgt[0 * NH + jf];
            nx1 = xgt[1 * NH + jf];
            nx2 = xgt[2 * NH + jf];
            nx3 = xgt[3 * NH + jf];
        }

        const int c = tid >> 5;
        // ---- half 1: rows 0..7 (gates i, f) ----
#pragma unroll
        for (int r2 = 0; r2 < 8; ++r2) {
            float2 u0 = unpack2(acc[r2][0]);
            float2 u1 = unpack2(acc[r2][1]);
            red2[(r2 << 10) + (c << 6) + b0]      = u0.x + u0.y;
            red2[(r2 << 10) + (c << 6) + b0 + 32] = u1.x + u1.y;
        }
        __syncthreads();
        float gi = x0, gf = x1;
        if (fin) {
            const float* p0 = &red2[((0 * 4 + fj) << 10) + fb];
            const float* p1 = &red2[((1 * 4 + fj) << 10) + fb];
            float a0 = 0.f, a1 = 0.f, a2 = 0.f, a3 = 0.f;
            float d0 = 0.f, d1 = 0.f, d2 = 0.f, d3 = 0.f;
#pragma unroll
            for (int cc = 0; cc < 16; cc += 4) {
                a0 += p0[(cc + 0) << 6]; a1 += p0[(cc + 1) << 6];
                a2 += p0[(cc + 2) << 6]; a3 += p0[(cc + 3) << 6];
                d0 += p1[(cc + 0) << 6]; d1 += p1[(cc + 1) << 6];
                d2 += p1[(cc + 2) << 6]; d3 += p1[(cc + 3) << 6];
            }
            gi += (a0 + a1) + (a2 + a3);
            gf += (d0 + d1) + (d2 + d3);
        }
        __syncthreads();
        // ---- half 2: rows 8..15 (gates g, o) ----
#pragma unroll
        for (int r2 = 8; r2 < 16; ++r2) {
            float2 u0 = unpack2(acc[r2][0]);
            float2 u1 = unpack2(acc[r2][1]);
            red2[((r2 - 8) << 10) + (c << 6) + b0]      = u0.x + u0.y;
            red2[((r2 - 8) << 10) + (c << 6) + b0 + 32] = u1.x + u1.y;
        }
        __syncthreads();
        if (fin) {
            float gg = x2, go = x3;
            const float* p2 = &red2[((0 * 4 + fj) << 10) + fb];
            const float* p3 = &red2[((1 * 4 + fj) << 10) + fb];
            float a0 = 0.f, a1 = 0.f, a2 = 0.f, a3 = 0.f;
            float d0 = 0.f, d1 = 0.f, d2 = 0.f, d3 = 0.f;
#pragma unroll
            for (int cc = 0; cc < 16; cc += 4) {
                a0 += p2[(cc + 0) << 6]; a1 += p2[(cc + 1) << 6];
                a2 += p2[(cc + 2) << 6]; a3 += p2[(cc + 3) << 6];
                d0 += p3[(cc + 0) << 6]; d1 += p3[(cc + 1) << 6];
                d2 += p3[(cc + 2) << 6]; d3 += p3[(cc + 3) << 6];
            }
            gg += (a0 + a1) + (a2 + a3);
            go += (d0 + d1) + (d2 + d3);

            float iv = 1.f / (1.f + __expf(-gi));
            float fv = 1.f / (1.f + __expf(-gf));
            float gv = 2.f / (1.f + __expf(-2.f * gg)) - 1.f;
            float ov = 1.f / (1.f + __expf(-go));
            cs = fv * cs + iv * gv;
            float hn = ov * (2.f / (1.f + __expf(-2.f * cs)) - 1.f);
            hx[fj * 64 + fb] = hn;
        }
        __syncthreads();
        if (tid < 64) {      // float4 assemble: h exchange + output (+ h_T)
            float4 vv = make_float4(hx[tid], hx[64 + tid], hx[128 + tid], hx[192 + tid]);
            *(float4*)&g_hbuf[rd ^ 1][blockIdx.x * 256 + tid * 4] = vv;
            *(float4*)&out[((long long)tid * NT + t) * NH + j0] = vv;
            if (tail && t == NT - 1)
                *(float4*)&out[(long long)NB * NT * NH + tid * NH + j0] = vv;
        }
        x0 = nx0; x1 = nx1; x2 = nx2; x3 = nx3;

        // grid barrier
        __syncthreads();
        if (tid == 0) bar_wait(bar_arrive());
        __syncthreads();
        rd ^= 1;
    }

    if (tail && fin)
        out[(long long)NB * NT * NH + NB * NH + fb * NH + jf] = cs;   // c_T
}

// ---------------- launch ----------------
extern "C" void kernel_launch(void* const* d_in, const int* in_sizes, int n_in,
                              void* d_out, int out_size) {
    const float* x   = (const float*)d_in[0];
    const float* h0  = (const float*)d_in[1];
    const float* c0  = (const float*)d_in[2];
    const float* Wih = (const float*)d_in[3];
    const float* Whh = (const float*)d_in[4];
    const float* bih = (const float*)d_in[5];
    const float* bhh = (const float*)d_in[6];
    float* out = (float*)d_out;

    gemm_xg<<<dim3(16, 256), 256>>>(x, Wih, bih, bhh);
    int tail = (out_size >= NB * NT * NH + 2 * NB * NH) ? 1 : 0;
    lstm_steps<<<GRID_R, 512>>>(Whh, h0, c0, out, tail);
}

// round 12
// speedup vs baseline: 1.5347x; 1.0305x over previous
#include <cuda_runtime.h>

#define NB 64
#define NT 512
#define NI 512
#define NH 512
#define NG 2048      // 4*H
#define GRID_R 256   // recurrent persistent CTAs (2 per SM, 148 SMs -> fits)

// ---------------- device scratch (static: no allocs allowed) ----------------
__device__ float g_xg[(long long)NT * NB * NG];   // [t][b][g]  (256 MB)
__device__ float g_hbuf[2][NH * NB];              // [k4][b][4j] packed quads
__device__ unsigned g_grp[16 * 32];               // 16 group counters, 128B apart
__device__ unsigned g_root[32];                   // root counter (padded line)

// ---------------- f32x2 packed-FMA helpers (Blackwell FFMA2) ----------------
__device__ __forceinline__ unsigned long long dup2(float x) {
    unsigned long long r;
    asm("mov.b64 %0, {%1,%1};" : "=l"(r) : "f"(x));
    return r;
}
__device__ __forceinline__ void fma2(unsigned long long& d,
                                     unsigned long long a,
                                     unsigned long long b) {
    asm("fma.rn.f32x2 %0, %1, %2, %0;" : "+l"(d) : "l"(a), "l"(b));
}
__device__ __forceinline__ float2 unpack2(unsigned long long v) {
    float lo, hi;
    asm("mov.b64 {%0,%1}, %2;" : "=f"(lo), "=f"(hi) : "l"(v));
    return make_float2(lo, hi);
}

// ---------------- two-level grid barrier (acq_rel atomics, replay-safe) -----
// 256 CTAs: 16 groups x 16 CTAs; root gains 16 per epoch.
__device__ __forceinline__ unsigned bar_arrive() {
    unsigned* grp = &g_grp[(blockIdx.x & 15) << 5];
    unsigned a;
    asm volatile("atom.acq_rel.gpu.global.add.u32 %0, [%1], 1;"
                 : "=r"(a) : "l"(grp) : "memory");
    if ((a & 15u) == 15u)                    // last of 16-CTA group
        asm volatile("red.release.gpu.global.add.u32 [%0], 1;"
                     :: "l"(g_root) : "memory");
    return ((a >> 4) + 1u) * 16u;            // 16 groups per epoch
}
__device__ __forceinline__ void bar_wait(unsigned target) {
    unsigned v;
    do {
        asm volatile("ld.acquire.gpu.global.u32 %0, [%1];"
                     : "=r"(v) : "l"(g_root) : "memory");
    } while ((int)(v - target) < 0);
}

// ---------------- xg GEMM: [32768,512] x [512,2048]^T -> g_xg[t][b][g] -------
#define STS_TILE(bufi)                                                         \
    do {                                                                       \
        As[bufi][ks + 0][r] = ra0.x; As[bufi][ks + 1][r] = ra0.y;              \
        As[bufi][ks + 2][r] = ra0.z; As[bufi][ks + 3][r] = ra0.w;              \
        As[bufi][ks + 4][r] = ra1.x; As[bufi][ks + 5][r] = ra1.y;              \
        As[bufi][ks + 6][r] = ra1.z; As[bufi][ks + 7][r] = ra1.w;              \
        Bs[bufi][ks + 0][r] = rb0.x; Bs[bufi][ks + 1][r] = rb0.y;              \
        Bs[bufi][ks + 2][r] = rb0.z; Bs[bufi][ks + 3][r] = rb0.w;              \
        Bs[bufi][ks + 4][r] = rb1.x; Bs[bufi][ks + 5][r] = rb1.y;              \
        Bs[bufi][ks + 6][r] = rb1.z; Bs[bufi][ks + 7][r] = rb1.w;              \
    } while (0)

__global__ __launch_bounds__(256, 2) void gemm_xg(const float* __restrict__ x,
                                                  const float* __restrict__ Wih,
                                                  const float* __restrict__ bih,
                                                  const float* __restrict__ bhh) {
    __shared__ __align__(16) float As[2][16][132];
    __shared__ __align__(16) float Bs[2][16][132];

    const int tid = threadIdx.x;
    const int n0 = blockIdx.x * 128;
    const int m0 = blockIdx.y * 128;
    const int tm = tid >> 4;
    const int tn = tid & 15;
    const int r  = tid >> 1;
    const int ks = (tid & 1) * 8;

    const float* pa = x   + (long long)(m0 + r) * NI + ks;
    const float* pb = Wih + (long long)(n0 + r) * NI + ks;

    unsigned long long acc[8][4];
#pragma unroll
    for (int i = 0; i < 8; ++i)
#pragma unroll
        for (int j = 0; j < 4; ++j) acc[i][j] = 0ull;

    float4 ra0, ra1, rb0, rb1;
    ra0 = *(const float4*)(pa);
    ra1 = *(const float4*)(pa + 4);
    rb0 = *(const float4*)(pb);
    rb1 = *(const float4*)(pb + 4);
    STS_TILE(0);
    __syncthreads();

#pragma unroll 1
    for (int kt = 0; kt < 32; ++kt) {
        const int buf = kt & 1;
        if (kt < 31) {
            const float* qa = pa + (kt + 1) * 16;
            const float* qb = pb + (kt + 1) * 16;
            ra0 = *(const float4*)(qa);
            ra1 = *(const float4*)(qa + 4);
            rb0 = *(const float4*)(qb);
            rb1 = *(const float4*)(qb + 4);
        }
#pragma unroll
        for (int kk = 0; kk < 16; ++kk) {
            float4 a0 = *(const float4*)&As[buf][kk][tm * 8];
            float4 a1 = *(const float4*)&As[buf][kk][tm * 8 + 4];
            ulonglong2 b01 = *(const ulonglong2*)&Bs[buf][kk][tn * 8];
            ulonglong2 b23 = *(const ulonglong2*)&Bs[buf][kk][tn * 8 + 4];
            float av[8] = {a0.x, a0.y, a0.z, a0.w, a1.x, a1.y, a1.z, a1.w};
            unsigned long long bp[4] = {b01.x, b01.y, b23.x, b23.y};
#pragma unroll
            for (int i = 0; i < 8; ++i) {
                unsigned long long ad = dup2(av[i]);
                fma2(acc[i][0], ad, bp[0]);
                fma2(acc[i][1], ad, bp[1]);
                fma2(acc[i][2], ad, bp[2]);
                fma2(acc[i][3], ad, bp[3]);
            }
        }
        if (kt < 31) {
            const int nb = buf ^ 1;
            STS_TILE(nb);
            __syncthreads();
        }
    }

    // Epilogue: +bias, write g_xg[t][b][g] — 8 gate-cols contiguous: coalesced
    float bias_[8];
#pragma unroll
    for (int j = 0; j < 8; ++j) {
        int n = n0 + tn * 8 + j;
        bias_[j] = bih[n] + bhh[n];
    }
#pragma unroll
    for (int i = 0; i < 8; ++i) {
        int m  = m0 + tm * 8 + i;
        int bb = m >> 9;           // batch
        int t  = m & (NT - 1);     // timestep
        float* orow = g_xg + ((long long)t * NB + bb) * NG + n0 + tn * 8;
        float2 v0 = unpack2(acc[i][0]);
        float2 v1 = unpack2(acc[i][1]);
        float2 v2 = unpack2(acc[i][2]);
        float2 v3 = unpack2(acc[i][3]);
        float4 o0 = make_float4(v0.x + bias_[0], v0.y + bias_[1],
                                v1.x + bias_[2], v1.y + bias_[3]);
        float4 o1 = make_float4(v2.x + bias_[4], v2.y + bias_[5],
                                v3.x + bias_[6], v3.y + bias_[7]);
        *(float4*)orow       = o0;
        *(float4*)(orow + 4) = o1;
    }
}

// ---------------- persistent recurrent kernel (2 CTAs / SM) -----------------
// CTA owns H-columns [2*bid, 2*bid+2). 256 thr = 8 warps; warp w = k-slice
// [w*64, w*64+64) (16 k4). Lane covers 2 batch elems (b0, b0+32), all 8
// (gate,j) rows: one W LDS.128 feeds 4 FFMA2. 8 k-partials reduced via smem;
// fin threads (tid<128: fb=tid&63, fj=tid>>6) finalize the cell.
__global__ __launch_bounds__(256, 2) void lstm_steps(const float* __restrict__ Whh,
                                                     const float* __restrict__ h0,
                                                     const float* __restrict__ c0,
                                                     float* __restrict__ out,
                                                     int tail) {
    __shared__ __align__(16) float wsm2[128 * 8 * 4];    // 16 KB W slice
    __shared__ __align__(16) float red[8 * 8 * 64];      // 16 KB [row][c][b]
    __shared__ float hx[128];

    const int tid   = threadIdx.x;
    const int b0    = tid & 31;
    const int kbase = (tid >> 5) * 16;      // warp's first k4
    const int fin   = tid < 128;
    const int fb    = tid & 63;
    const int fj    = (tid >> 6) & 1;
    const int bid   = blockIdx.x;
    const int j0    = bid * 2;
    const int jf    = j0 + fj;

    // Stage W_hh slice: quad (k4*8 + row) = Whh[q*NH + j0+cc][4k4..4k4+3],
    // row = q*2+cc (4 gates x 2 cols)
    for (int idx = tid; idx < 128 * 8; idx += 256) {
        int k4  = idx >> 3;
        int row = idx & 7;
        int q   = row >> 1;
        int cc  = row & 1;
        *(float4*)&wsm2[idx * 4] =
            *(const float4*)&Whh[(long long)(q * NH + j0 + cc) * NH + k4 * 4];
    }

    // Repack h0: CTA bid owns cols 2bid..2bid+1 -> half of quad k4 = bid>>1
    if (tid < 128) {
        int b  = tid >> 1;
        int jj = tid & 1;
        g_hbuf[0][(bid >> 1) * 256 + b * 4 + (bid & 1) * 2 + jj] =
            h0[b * NH + j0 + jj];
    }

    float cs = 0.f, x0 = 0.f, x1 = 0.f, x2 = 0.f, x3 = 0.f;
    if (fin) {
        cs = c0[fb * NH + jf];
        const float* xg0 = g_xg + (long long)fb * NG;    // t = 0
        x0 = xg0[0 * NH + jf];
        x1 = xg0[1 * NH + jf];
        x2 = xg0[2 * NH + jf];
        x3 = xg0[3 * NH + jf];
    }
    int rd = 0;

    // initial full barrier: h0 repack + wsm2 staging visible everywhere
    __syncthreads();
    if (tid == 0) bar_wait(bar_arrive());
    __syncthreads();

    const ulonglong2* wq = (const ulonglong2*)wsm2 + (kbase << 3);

    for (int t = 0; t < NT; ++t) {
        const ulonglong2* hb2 = (const ulonglong2*)g_hbuf[rd];

        unsigned long long acc[8][2];
#pragma unroll
        for (int r2 = 0; r2 < 8; ++r2) { acc[r2][0] = 0ull; acc[r2][1] = 0ull; }

        // depth-4 h prefetch ring (MLP 8 up front)
        ulonglong2 hra[4], hrc[4];
#pragma unroll
        for (int i = 0; i < 4; ++i) {
            hra[i] = hb2[(kbase + i) * 64 + b0];
            hrc[i] = hb2[(kbase + i) * 64 + b0 + 32];
        }
#pragma unroll
        for (int k4 = 0; k4 < 16; ++k4) {
            ulonglong2 hA = hra[k4 & 3], hB = hrc[k4 & 3];
            if (k4 < 12) {
                hra[k4 & 3] = hb2[(kbase + k4 + 4) * 64 + b0];
                hrc[k4 & 3] = hb2[(kbase + k4 + 4) * 64 + b0 + 32];
            }
            const ulonglong2* wr = wq + (k4 << 3);
#pragma unroll
            for (int r2 = 0; r2 < 8; ++r2) {
                ulonglong2 w = wr[r2];                 // broadcast LDS.128
                fma2(acc[r2][0], hA.x, w.x);
                fma2(acc[r2][0], hA.y, w.y);
                fma2(acc[r2][1], hB.x, w.x);
                fma2(acc[r2][1], hB.y, w.y);
            }
        }

        // next step's xg prefetch (h-independent) — hidden behind reduction
        float nx0 = x0, nx1 = x1, nx2 = x2, nx3 = x3;
        if (fin) {
            int tn2 = (t + 1 < NT) ? t + 1 : t;
            const float* xgt = g_xg + ((long long)tn2 * NB + fb) * NG;
            nx0 = xgt[0 * NH + jf];
            nx1 = xgt[1 * NH + jf];
            nx2 = xgt[2 * NH + jf];
            nx3 = xgt[3 * NH + jf];
        }

        const int c = tid >> 5;
        // write partials: red[row][c][b]  (8 rows x 8 c x 64 b)
#pragma unroll
        for (int r2 = 0; r2 < 8; ++r2) {
            float2 u0 = unpack2(acc[r2][0]);
            float2 u1 = unpack2(acc[r2][1]);
            red[(r2 << 9) + (c << 6) + b0]      = u0.x + u0.y;
            red[(r2 << 9) + (c << 6) + b0 + 32] = u1.x + u1.y;
        }
        __syncthreads();

        if (fin) {
            float g4[4];
#pragma unroll
            for (int q = 0; q < 4; ++q) {
                const float* rp = &red[((q * 2 + fj) << 9) + fb];
                float s0 = 0.f, s1 = 0.f, s2 = 0.f, s3 = 0.f;
                s0 = rp[0 << 6] + rp[4 << 6];
                s1 = rp[1 << 6] + rp[5 << 6];
                s2 = rp[2 << 6] + rp[6 << 6];
                s3 = rp[3 << 6] + rp[7 << 6];
                g4[q] = (s0 + s1) + (s2 + s3);
            }
            float gi = g4[0] + x0;
            float gf = g4[1] + x1;
            float gg = g4[2] + x2;
            float go = g4[3] + x3;

            float iv = 1.f / (1.f + __expf(-gi));
            float fv = 1.f / (1.f + __expf(-gf));
            float gv = 2.f / (1.f + __expf(-2.f * gg)) - 1.f;
            float ov = 1.f / (1.f + __expf(-go));
            cs = fv * cs + iv * gv;
            float hn = ov * (2.f / (1.f + __expf(-2.f * cs)) - 1.f);
            hx[fj * 64 + fb] = hn;
        }
        __syncthreads();

        if (tid < 64) {      // float2 assemble: h exchange + output (+ h_T)
            float2 vv = make_float2(hx[tid], hx[64 + tid]);
            *(float2*)&g_hbuf[rd ^ 1][(bid >> 1) * 256 + tid * 4 + (bid & 1) * 2] = vv;
            *(float2*)&out[((long long)tid * NT + t) * NH + j0] = vv;
            if (tail && t == NT - 1)
                *(float2*)&out[(long long)NB * NT * NH + tid * NH + j0] = vv;
        }
        x0 = nx0; x1 = nx1; x2 = nx2; x3 = nx3;

        // grid barrier
        __syncthreads();
        if (tid == 0) bar_wait(bar_arrive());
        __syncthreads();
        rd ^= 1;
    }

    if (tail && fin)
        out[(long long)NB * NT * NH + NB * NH + fb * NH + jf] = cs;   // c_T
}

// ---------------- launch ----------------
extern "C" void kernel_launch(void* const* d_in, const int* in_sizes, int n_in,
                              void* d_out, int out_size) {
    const float* x   = (const float*)d_in[0];
    const float* h0  = (const float*)d_in[1];
    const float* c0  = (const float*)d_in[2];
    const float* Wih = (const float*)d_in[3];
    const float* Whh = (const float*)d_in[4];
    const float* bih = (const float*)d_in[5];
    const float* bhh = (const float*)d_in[6];
    float* out = (float*)d_out;

    gemm_xg<<<dim3(16, 256), 256>>>(x, Wih, bih, bhh);
    int tail = (out_size >= NB * NT * NH + 2 * NB * NH) ? 1 : 0;
    lstm_steps<<<GRID_R, 256>>>(Whh, h0, c0, out, tail);
}